// round 2
// baseline (speedup 1.0000x reference)
#include <cuda_runtime.h>
#include <math.h>

#define NB   4
#define LSEQ 4096
#define EMB  1024
#define NH   16
#define HD   64
#define WIN  256
#define OV   32
#define KWIN 320      // WIN + 2*OV
#define NWIN 16       // LSEQ / WIN

// Scratch (device globals -- no allocation allowed)
__device__ float g_q[(size_t)NB * LSEQ * EMB];
__device__ float g_k[(size_t)NB * LSEQ * EMB];
__device__ float g_v[(size_t)NB * LSEQ * EMB];
__device__ float g_att[(size_t)NB * LSEQ * EMB];

// ---------------------------------------------------------------------------
// Kernel 1: fused q/k/v per-head projection.
// out[r, h, e] = sum_d X[r, h, d] * W[e, d]   (same 64x64 W for every head)
// grid: (NB*LSEQ/64, NH, 3), block: 256
// ---------------------------------------------------------------------------
__global__ __launch_bounds__(256) void proj_kernel(
    const float* __restrict__ vals, const float* __restrict__ keys,
    const float* __restrict__ qrs,
    const float* __restrict__ Wv, const float* __restrict__ Wk,
    const float* __restrict__ Wq)
{
    __shared__ float sW[64][65];
    __shared__ float sX[64][65];

    const float* X; const float* W; float* O;
    switch (blockIdx.z) {
        case 0:  X = vals; W = Wv; O = g_v; break;
        case 1:  X = keys; W = Wk; O = g_k; break;
        default: X = qrs;  W = Wq; O = g_q; break;
    }
    const int h  = blockIdx.y;
    const size_t r0 = (size_t)blockIdx.x * 64;
    const int t  = threadIdx.x;

    for (int i = t; i < 64 * 64; i += 256) sW[i >> 6][i & 63] = W[i];
    for (int i = t; i < 64 * 64; i += 256) {
        int r = i >> 6, dd = i & 63;
        sX[r][dd] = X[(r0 + r) * EMB + h * HD + dd];
    }
    __syncthreads();

    const int tx = t & 15, ty = t >> 4;
    float acc[4][4] = {};
    #pragma unroll 8
    for (int dd = 0; dd < 64; dd++) {
        float a[4], b[4];
        #pragma unroll
        for (int i = 0; i < 4; i++) a[i] = sX[ty * 4 + i][dd];
        #pragma unroll
        for (int j = 0; j < 4; j++) b[j] = sW[tx * 4 + j][dd];
        #pragma unroll
        for (int i = 0; i < 4; i++)
            #pragma unroll
            for (int j = 0; j < 4; j++) acc[i][j] += a[i] * b[j];
    }

    #pragma unroll
    for (int i = 0; i < 4; i++)
        #pragma unroll
        for (int j = 0; j < 4; j++)
            O[(r0 + ty * 4 + i) * EMB + h * HD + tx * 4 + j] = acc[i][j];
}

// ---------------------------------------------------------------------------
// Kernel 2: overlapping-window attention.
// One block per (window, head, batch). 256 threads = 1 query/thread.
// K/V tiles resident in dynamic smem (2 * 320 * 64 * 4B = 160 KB).
// Flash-style chunked online softmax, scores kept in registers.
// ---------------------------------------------------------------------------
__global__ __launch_bounds__(256, 1) void attn_kernel(const int* __restrict__ mask)
{
    extern __shared__ float sm[];
    float* sK = sm;                 // KWIN * HD
    float* sV = sm + KWIN * HD;     // KWIN * HD

    const int w  = blockIdx.x;
    const int h  = blockIdx.y;
    const int nb = blockIdx.z;
    const int t  = threadIdx.x;
    const size_t qbase = (size_t)nb * LSEQ + (size_t)w * WIN;

    // --- Stage Q tile through sK with rotation swizzle (coalesced gmem,
    //     conflict-free smem), pull this thread's query row into registers.
    for (int i = t; i < WIN * HD; i += 256) {
        int r = i >> 6, dd = i & 63;
        sK[r * 64 + ((dd + r) & 63)] = g_q[(qbase + r) * EMB + h * HD + dd];
    }
    __syncthreads();
    float q[64];
    #pragma unroll
    for (int i = 0; i < 64; i++) q[i] = sK[t * 64 + ((i + t) & 63)];
    __syncthreads();

    // --- Load K/V tiles (zero-padded outside the sequence).
    const float4* gk4 = (const float4*)g_k;
    const float4* gv4 = (const float4*)g_v;
    float4* sK4 = (float4*)sK;
    float4* sV4 = (float4*)sV;
    for (int i = t; i < KWIN * (HD / 4); i += 256) {
        int j = i >> 4, u = i & 15;
        int tok = w * WIN + j - OV;
        float4 kk = make_float4(0.f, 0.f, 0.f, 0.f);
        float4 vv = make_float4(0.f, 0.f, 0.f, 0.f);
        if ((unsigned)tok < (unsigned)LSEQ) {
            size_t idx = (((size_t)nb * LSEQ + tok) * EMB + h * HD) / 4 + u;
            kk = gk4[idx];
            vv = gv4[idx];
        }
        sK4[i] = kk;
        sV4[i] = vv;
    }
    __syncthreads();

    const int qtok = w * WIN + t;
    const bool qv  = mask[(size_t)nb * LSEQ + qtok] != 0;

    float m = -INFINITY, l = 0.f;
    float acc[64];
    #pragma unroll
    for (int i = 0; i < 64; i++) acc[i] = 0.f;

    for (int c = 0; c < KWIN / 16; c++) {
        float s[16];
        float cmax = -INFINITY;
        #pragma unroll
        for (int jj = 0; jj < 16; jj++) {
            const int j = c * 16 + jj;
            const float4* kr = (const float4*)(sK + j * 64);
            float s0 = 0.f, s1 = 0.f, s2 = 0.f, s3 = 0.f;
            #pragma unroll
            for (int u = 0; u < 16; u++) {
                float4 k4 = kr[u];                       // broadcast LDS.128
                s0 += q[4 * u + 0] * k4.x;
                s1 += q[4 * u + 1] * k4.y;
                s2 += q[4 * u + 2] * k4.z;
                s3 += q[4 * u + 3] * k4.w;
            }
            float sc = ((s0 + s1) + (s2 + s3)) * 0.125f;  // 1/sqrt(64)
            if (!qv) sc = -1.25e9f;                        // -1e10 / 8
            int tok = w * WIN + j - OV;
            if ((unsigned)tok >= (unsigned)LSEQ) sc = -INFINITY;
            s[jj] = sc;
            cmax = fmaxf(cmax, sc);
        }
        const float mn = fmaxf(m, cmax);
        if (mn == -INFINITY) continue;     // whole chunk invalid (edge windows)
        const float corr = __expf(m - mn); // exp(-inf) = 0 handles m = -inf
        l *= corr;
        #pragma unroll
        for (int i = 0; i < 64; i++) acc[i] *= corr;
        #pragma unroll
        for (int jj = 0; jj < 16; jj++) {
            const int j = c * 16 + jj;
            const float p = __expf(s[jj] - mn);
            l += p;
            const float4* vr = (const float4*)(sV + j * 64);
            #pragma unroll
            for (int u = 0; u < 16; u++) {
                float4 v4 = vr[u];                       // broadcast LDS.128
                acc[4 * u + 0] += p * v4.x;
                acc[4 * u + 1] += p * v4.y;
                acc[4 * u + 2] += p * v4.z;
                acc[4 * u + 3] += p * v4.w;
            }
        }
        m = mn;
    }

    const float inv = (l > 0.f) ? (1.f / l) : 0.f;

    // --- Stage output back through sK (swizzled) for coalesced gmem writes.
    __syncthreads();
    #pragma unroll
    for (int i = 0; i < 64; i++) sK[t * 64 + ((i + t) & 63)] = acc[i] * inv;
    __syncthreads();
    for (int i = t; i < WIN * HD; i += 256) {
        int r = i >> 6, dd = i & 63;
        g_att[(qbase + r) * EMB + h * HD + dd] = sK[r * 64 + ((dd + r) & 63)];
    }
}

// ---------------------------------------------------------------------------
// Kernel 3: output projection  out = g_att @ Wf^T + bf
// 128x128x16 smem-tiled sgemm, 8x8 per thread.
// grid: (EMB/128, NB*LSEQ/128), block: 256
// ---------------------------------------------------------------------------
__global__ __launch_bounds__(256) void out_gemm_kernel(
    const float* __restrict__ Wf, const float* __restrict__ bf,
    float* __restrict__ out)
{
    __shared__ float As[16][128];
    __shared__ float Bs[16][128];

    const int bn = blockIdx.x, bm = blockIdx.y;
    const int t  = threadIdx.x;
    const int tx = t & 15, ty = t >> 4;
    const size_t m0 = (size_t)bm * 128;
    const int e0 = bn * 128;

    float acc[8][8] = {};
    const int lrow = t >> 2, lpart = t & 3;

    for (int k0 = 0; k0 < EMB; k0 += 16) {
        #pragma unroll
        for (int p = 0; p < 2; p++) {
            int r = lrow + p * 64;
            float4 a4 = *(const float4*)&g_att[(m0 + r) * EMB + k0 + lpart * 4];
            As[lpart * 4 + 0][r] = a4.x;
            As[lpart * 4 + 1][r] = a4.y;
            As[lpart * 4 + 2][r] = a4.z;
            As[lpart * 4 + 3][r] = a4.w;
            float4 b4 = *(const float4*)&Wf[(size_t)(e0 + r) * EMB + k0 + lpart * 4];
            Bs[lpart * 4 + 0][r] = b4.x;
            Bs[lpart * 4 + 1][r] = b4.y;
            Bs[lpart * 4 + 2][r] = b4.z;
            Bs[lpart * 4 + 3][r] = b4.w;
        }
        __syncthreads();
        #pragma unroll
        for (int kk = 0; kk < 16; kk++) {
            float a[8], b[8];
            *(float4*)&a[0] = *(const float4*)&As[kk][ty * 8];
            *(float4*)&a[4] = *(const float4*)&As[kk][ty * 8 + 4];
            *(float4*)&b[0] = *(const float4*)&Bs[kk][tx * 8];
            *(float4*)&b[4] = *(const float4*)&Bs[kk][tx * 8 + 4];
            #pragma unroll
            for (int i = 0; i < 8; i++)
                #pragma unroll
                for (int j = 0; j < 8; j++) acc[i][j] += a[i] * b[j];
        }
        __syncthreads();
    }

    float bias[8];
    #pragma unroll
    for (int j = 0; j < 8; j++) bias[j] = bf[e0 + tx * 8 + j];
    #pragma unroll
    for (int i = 0; i < 8; i++) {
        size_t row = m0 + ty * 8 + i;
        #pragma unroll
        for (int j = 0; j < 8; j++)
            out[row * EMB + e0 + tx * 8 + j] = acc[i][j] + bias[j];
    }
}

// ---------------------------------------------------------------------------
extern "C" void kernel_launch(void* const* d_in, const int* in_sizes, int n_in,
                              void* d_out, int out_size)
{
    const float* vals = (const float*)d_in[0];
    const float* keys = (const float*)d_in[1];
    const float* qrs  = (const float*)d_in[2];
    const int*   mask = (const int*)d_in[3];
    const float* Wv   = (const float*)d_in[4];
    const float* Wk   = (const float*)d_in[5];
    const float* Wq   = (const float*)d_in[6];
    const float* Wf   = (const float*)d_in[7];
    const float* bf   = (const float*)d_in[8];
    float* out = (float*)d_out;

    const int attn_smem = 2 * KWIN * HD * (int)sizeof(float);  // 160 KB
    cudaFuncSetAttribute(attn_kernel,
                         cudaFuncAttributeMaxDynamicSharedMemorySize, attn_smem);

    proj_kernel<<<dim3(NB * LSEQ / 64, NH, 3), 256>>>(vals, keys, qrs, Wv, Wk, Wq);
    attn_kernel<<<dim3(NWIN, NH, NB), 256, attn_smem>>>(mask);
    out_gemm_kernel<<<dim3(EMB / 128, NB * LSEQ / 128), 256>>>(Wf, bf, out);
}